// round 4
// baseline (speedup 1.0000x reference)
#include <cuda_runtime.h>
#include <cstdint>

// out[i,j] = swap_mask[i,j] ? x[i, perm[i,j]] : x[i,j]
// B=16384 rows, F=2048 cols. One CTA per row; row staged in SMEM (8KB),
// gather resolved from SMEM, all global traffic fully coalesced 16B vectors.
// swap_mask arrives as int32 (harness materializes jax bool as int32).

#define N_FEAT   2048
#define THREADS  256
#define VEC_PER_THREAD (N_FEAT / 4 / THREADS)   // 2 float4 chunks per thread

__global__ __launch_bounds__(THREADS, 8)
void swap_corruption_kernel(const float* __restrict__ x,
                            const int* __restrict__ mask,
                            const int* __restrict__ perm,
                            float* __restrict__ out)
{
    __shared__ float srow[N_FEAT];

    const long long base = (long long)blockIdx.x * N_FEAT;

    // Stage the row: 2048 floats = 512 float4, 256 threads x 2
    const float4* __restrict__ x4 = reinterpret_cast<const float4*>(x + base);
    float4* s4 = reinterpret_cast<float4*>(srow);
#pragma unroll
    for (int c = 0; c < VEC_PER_THREAD; ++c) {
        s4[c * THREADS + threadIdx.x] = x4[c * THREADS + threadIdx.x];
    }
    __syncthreads();

    const int4*  __restrict__ p4 = reinterpret_cast<const int4*>(perm + base);
    const int4*  __restrict__ m4 = reinterpret_cast<const int4*>(mask + base);
    float4*      __restrict__ o4 = reinterpret_cast<float4*>(out + base);

#pragma unroll
    for (int c = 0; c < VEC_PER_THREAD; ++c) {
        const int v = c * THREADS + threadIdx.x;   // float4 index within row
        const int4 p = p4[v];
        const int4 m = m4[v];                      // one int32 bool per element
        const int j = v * 4;

        float4 r;
        r.x = m.x ? srow[p.x] : srow[j + 0];
        r.y = m.y ? srow[p.y] : srow[j + 1];
        r.z = m.z ? srow[p.z] : srow[j + 2];
        r.w = m.w ? srow[p.w] : srow[j + 3];
        o4[v] = r;
    }
}

extern "C" void kernel_launch(void* const* d_in, const int* in_sizes, int n_in,
                              void* d_out, int out_size)
{
    const float* x    = (const float*)d_in[0];
    const int*   mask = (const int*)d_in[1];
    const int*   perm = (const int*)d_in[2];
    float*       out  = (float*)d_out;

    const int batch = in_sizes[0] / N_FEAT;      // 16384
    swap_corruption_kernel<<<batch, THREADS>>>(x, mask, perm, out);
}

// round 6
// speedup vs baseline: 1.0090x; 1.0090x over previous
#include <cuda_runtime.h>
#include <cstdint>

// out[i,j] = swap_mask[i,j] ? x[i, perm[i,j]] : x[i,j]
// B=16384 rows, F=2048 cols. One CTA per row; row staged in SMEM (8KB).
// Optimization vs R3: perm int4 load predicated on mask (only ~34% of threads,
// ~57% of 32B sectors needed) -> perm DRAM traffic 128MB -> ~73MB.

#define N_FEAT   2048
#define THREADS  256
#define VEC_PER_THREAD (N_FEAT / 4 / THREADS)   // 2 float4 chunks per thread

__global__ __launch_bounds__(THREADS, 8)
void swap_corruption_kernel(const float* __restrict__ x,
                            const int* __restrict__ mask,
                            const int* __restrict__ perm,
                            float* __restrict__ out)
{
    __shared__ float srow[N_FEAT];

    const long long base = (long long)blockIdx.x * N_FEAT;

    const float4* __restrict__ x4 = reinterpret_cast<const float4*>(x + base);
    const int4*   __restrict__ p4 = reinterpret_cast<const int4*>(perm + base);
    const int4*   __restrict__ m4 = reinterpret_cast<const int4*>(mask + base);
    float4*       __restrict__ o4 = reinterpret_cast<float4*>(out + base);

    const int v0 = threadIdx.x;            // chunk 0 float4 index
    const int v1 = THREADS + threadIdx.x;  // chunk 1 float4 index

    // Issue mask loads and x staging loads up-front (keep MLP high)
    const int4  m0 = m4[v0];
    const int4  m1 = m4[v1];
    const float4 xa = x4[v0];
    const float4 xb = x4[v1];

    // Predicated perm loads: only fetch where a swap actually happens.
    int4 p0 = make_int4(0, 0, 0, 0);
    int4 p1 = make_int4(0, 0, 0, 0);
    if (m0.x | m0.y | m0.z | m0.w) p0 = p4[v0];
    if (m1.x | m1.y | m1.z | m1.w) p1 = p4[v1];

    // Stage the row into SMEM
    float4* s4 = reinterpret_cast<float4*>(srow);
    s4[v0] = xa;
    s4[v1] = xb;
    __syncthreads();

    {
        const int j = v0 * 4;
        float4 r;
        r.x = m0.x ? srow[p0.x] : xa.x;
        r.y = m0.y ? srow[p0.y] : xa.y;
        r.z = m0.z ? srow[p0.z] : xa.z;
        r.w = m0.w ? srow[p0.w] : xa.w;
        (void)j;
        o4[v0] = r;
    }
    {
        float4 r;
        r.x = m1.x ? srow[p1.x] : xb.x;
        r.y = m1.y ? srow[p1.y] : xb.y;
        r.z = m1.z ? srow[p1.z] : xb.z;
        r.w = m1.w ? srow[p1.w] : xb.w;
        o4[v1] = r;
    }
}

extern "C" void kernel_launch(void* const* d_in, const int* in_sizes, int n_in,
                              void* d_out, int out_size)
{
    const float* x    = (const float*)d_in[0];
    const int*   mask = (const int*)d_in[1];
    const int*   perm = (const int*)d_in[2];
    float*       out  = (float*)d_out;

    const int batch = in_sizes[0] / N_FEAT;      // 16384
    swap_corruption_kernel<<<batch, THREADS>>>(x, mask, perm, out);
}